// round 14
// baseline (speedup 1.0000x reference)
#include <cuda_runtime.h>
#include <math_constants.h>

#define NN   50000
#define EE   1600000
#define D    64
#define DE   16
#define CAP  128          // bucket capacity per node (17 sigma above mean deg 32)
#define ATT_SLOPE 0.2f
#define ACT_SLOPE 0.01f

typedef unsigned long long u64;
union F2U { u64 u; float2 f; };
union PS  { u64 u; struct { float p; int sr; } v; };
union QQ  { uint4 u4; PS ps[2]; };     // one LDS.128 -> two (p,sr) records
union U4P { uint4 u4; u64 pr[2]; };    // one LDS.128 -> two f32x2 pairs

__device__ __forceinline__ u64 fma2(u64 a, u64 b, u64 c) {
    u64 d; asm("fma.rn.f32x2 %0, %1, %2, %3;" : "=l"(d) : "l"(a), "l"(b), "l"(c));
    return d;
}
__device__ __forceinline__ u64 pack2(float x, float y) {
    F2U t; t.f = make_float2(x, y); return t.u;
}

// ---------------- scratch (device globals; no allocation allowed) -----------
__device__ float2 g_h [NN * 32];     // transformed features, dim pairs (2l,2l+1)
__device__ float2 g_c1[NN * 32];     // layer-1 output
__device__ float  g_hs[NN];
__device__ float  g_hd[NN];
__device__ int4   g_pack[NN * CAP];  // {unused, src, dot1(asint), dot2(asint)}
__device__ uint4  g_ea [NN * CAP * 4]; // edge_attr rows in BUCKET order (64B/edge)
__device__ int    g_cnt[NN];         // per-node edge count (cursor)
__device__ float  g_wea1[DE], g_wea2[DE];

// ---------------- prep: zero counters + wea = We@ae (merged: 1 launch) ------
__global__ void k_prep(const float* __restrict__ We1, const float* __restrict__ ae1,
                       const float* __restrict__ We2, const float* __restrict__ ae2) {
    int i = blockIdx.x * blockDim.x + threadIdx.x;
    if (i < NN) g_cnt[i] = 0;
    if (blockIdx.x == 0 && threadIdx.x < 2 * DE) {
        int t = threadIdx.x;
        if (t < DE) {
            float a = 0.f;
            #pragma unroll
            for (int d = 0; d < D; d++) a = fmaf(We1[t * D + d], ae1[d], a);
            g_wea1[t] = a;
        } else {
            int j = t - DE;
            float a = 0.f;
            #pragma unroll
            for (int d = 0; d < D; d++) a = fmaf(We2[j * D + d], ae2[d], a);
            g_wea2[j] = a;
        }
    }
}

// scatter into fixed buckets: packed meta record + eattr row in bucket order
__global__ void k_scatter(const int* __restrict__ src, const int* __restrict__ dst,
                          const float* __restrict__ eattr) {
    __shared__ float sw1[DE], sw2[DE];
    if (threadIdx.x < DE) sw1[threadIdx.x] = g_wea1[threadIdx.x];
    else if (threadIdx.x < 2 * DE) sw2[threadIdx.x - DE] = g_wea2[threadIdx.x - DE];
    __syncthreads();
    int i = blockIdx.x * blockDim.x + threadIdx.x;
    if (i < EE / 4) {
        int4 dv = ((const int4*)dst)[i];
        int4 sv = ((const int4*)src)[i];
        const int* dp = &dv.x;
        const int* sp = &sv.x;
        #pragma unroll
        for (int r = 0; r < 4; r++) {
            int e = 4 * i + r;
            const float4* ea4 = (const float4*)(eattr + (size_t)e * DE);
            float4 A = ea4[0], B = ea4[1], C = ea4[2], Dd = ea4[3];
            float d1 = 0.f, d2 = 0.f;
            #pragma unroll
            for (int k = 0; k < 4; k++) { d1 = fmaf((&A.x)[k],  sw1[k],      d1); d2 = fmaf((&A.x)[k],  sw2[k],      d2); }
            #pragma unroll
            for (int k = 0; k < 4; k++) { d1 = fmaf((&B.x)[k],  sw1[k + 4],  d1); d2 = fmaf((&B.x)[k],  sw2[k + 4],  d2); }
            #pragma unroll
            for (int k = 0; k < 4; k++) { d1 = fmaf((&C.x)[k],  sw1[k + 8],  d1); d2 = fmaf((&C.x)[k],  sw2[k + 8],  d2); }
            #pragma unroll
            for (int k = 0; k < 4; k++) { d1 = fmaf((&Dd.x)[k], sw1[k + 12], d1); d2 = fmaf((&Dd.x)[k], sw2[k + 12], d2); }
            int dn = dp[r];
            int p = atomicAdd(&g_cnt[dn], 1);
            int slot = dn * CAP + p;
            g_pack[slot] = make_int4(0, sp[r], __float_as_int(d1), __float_as_int(d2));
            uint4* o = &g_ea[(size_t)slot * 4];
            o[0] = *(const uint4*)&A;  o[1] = *(const uint4*)&B;
            o[2] = *(const uint4*)&C;  o[3] = *(const uint4*)&Dd;
        }
    }
}

// ---------------- feature transform: h = x@W, hs = h.a_s, hd = h.a_d --------
__global__ void __launch_bounds__(256) k_feat(const float* __restrict__ xin,
                                              const float* __restrict__ W,
                                              const float* __restrict__ a_s,
                                              const float* __restrict__ a_d,
                                              int use_c1) {
    __shared__ u64 sW2[D * 32];
    __shared__ float sx[8][4][D];
    __shared__ u64 sas2[32], sad2[32];
    const float* __restrict__ x = use_c1 ? (const float*)g_c1 : xin;
    int tid = threadIdx.x;
    for (int i = tid; i < D * 32; i += 256) sW2[i] = ((const u64*)W)[i];
    if (tid < 32) { sas2[tid] = ((const u64*)a_s)[tid]; sad2[tid] = ((const u64*)a_d)[tid]; }
    __syncthreads();
    int warp = tid >> 5, lane = tid & 31;
    F2U asv; asv.u = sas2[lane];
    F2U adv; adv.u = sad2[lane];
    int gw = blockIdx.x * 8 + warp;
    int nw = gridDim.x * 8;
    for (int r0 = gw * 4; r0 < NN; r0 += nw * 4) {
        #pragma unroll
        for (int r = 0; r < 4; r++) {
            int row = r0 + r;
            if (row < NN) {
                sx[warp][r][lane]      = x[row * D + lane];
                sx[warp][r][lane + 32] = x[row * D + lane + 32];
            }
        }
        __syncwarp();
        F2U acc[4];
        #pragma unroll
        for (int r = 0; r < 4; r++) acc[r].u = 0ull;
        #pragma unroll
        for (int k = 0; k < D; k++) {
            u64 wp = sW2[k * 32 + lane];
            #pragma unroll
            for (int r = 0; r < 4; r++) {
                float xv = sx[warp][r][k];
                acc[r].u = fma2(pack2(xv, xv), wp, acc[r].u);
            }
        }
        #pragma unroll
        for (int r = 0; r < 4; r++) {
            int row = r0 + r;
            if (row < NN) {
                g_h[row * 32 + lane] = acc[r].f;
                float ps = acc[r].f.x * asv.f.x + acc[r].f.y * asv.f.y;
                float pd = acc[r].f.x * adv.f.x + acc[r].f.y * adv.f.y;
                #pragma unroll
                for (int o = 16; o; o >>= 1) {
                    ps += __shfl_xor_sync(0xffffffffu, ps, o);
                    pd += __shfl_xor_sync(0xffffffffu, pd, o);
                }
                if (lane == 0) { g_hs[row] = ps; g_hd[row] = pd; }
            }
        }
        __syncwarp();
    }
}

// ---------------- fused GAT: sequential-eattr pipeline + LDS.128 consume -----
// warp per dst node; lane owns dim pair (2l,2l+1); We in registers.
// eattr for a chunk is ONE contiguous 2KB block (bucket order): staged with
// 4 coalesced LDG.128 + 4 STS.128, prefetched to registers one chunk ahead.
__global__ void __launch_bounds__(256, 2) k_gat(const float* __restrict__ We,
                                                const float* __restrict__ bias,
                                                float* __restrict__ dout,
                                                int layer2) {
    __shared__ uint4 sea[8][128];     // [warp][linear 2KB chunk copy]
    __shared__ u64   ssp[8][34];      // packed (p,sr); paired LDS.128 reads
    __shared__ u64   sb2[32];
    float* __restrict__ out = layer2 ? dout : (float*)g_c1;
    int tid = threadIdx.x, lane = tid & 31, warp = tid >> 5;
    if (tid < 32) sb2[tid] = ((const u64*)bias)[tid];
    __syncthreads();

    // register-resident We k-pairs for this lane's two dims
    int d0 = 2 * lane, d1 = d0 + 1;
    u64 wd0[8], wd1[8];
    #pragma unroll
    for (int j = 0; j < 8; j++) {
        wd0[j] = pack2(We[(2 * j) * D + d0], We[(2 * j + 1) * D + d0]);
        wd1[j] = pack2(We[(2 * j) * D + d1], We[(2 * j + 1) * D + d1]);
    }
    F2U bv; bv.u = sb2[lane];

    int gw = blockIdx.x * 8 + warp;
    int nw = gridDim.x * 8;

    for (int n = gw; n < NN; n += nw) {
        int beg = n * CAP, end = beg + g_cnt[n];
        float o0, o1;
        if (beg == end) {
            o0 = 0.f; o1 = 0.f;
        } else {
            float hdn = g_hd[n];
            // ---- pass 1: segment max of logits (lane-parallel) --------------
            float mmax = -CUDART_INF_F;
            for (int idx = beg + lane; idx < end; idx += 32) {
                int4 v = g_pack[idx];
                float dv = layer2 ? __int_as_float(v.w) : __int_as_float(v.z);
                float l = g_hs[v.y] + hdn + dv;
                l = fmaxf(l, ATT_SLOPE * l);            // leaky_relu(l, 0.2)
                mmax = fmaxf(mmax, l);
            }
            #pragma unroll
            for (int o = 16; o; o >>= 1)
                mmax = fmaxf(mmax, __shfl_xor_sync(0xffffffffu, mmax, o));

            // ---- pass 2: pipelined sequential stage + aggregate -------------
            float s = 0.f;
            float a0 = -CUDART_INF_F, a1 = -CUDART_INF_F;

            // stage chunk 0 (coalesced linear copy + metadata)
            {
                int cnt0 = min(32, end - beg);
                int idx = beg + lane;
                if (idx < end) {
                    int4 v = g_pack[idx];
                    float dv = layer2 ? __int_as_float(v.w) : __int_as_float(v.z);
                    float l = g_hs[v.y] + hdn + dv;
                    l = fmaxf(l, ATT_SLOPE * l);
                    float p = __expf(l - mmax);
                    s += p;
                    PS ps; ps.v.p = p; ps.v.sr = v.y;
                    ssp[warp][lane] = ps.u;
                }
                const uint4* srcp = &g_ea[(size_t)beg * 4];
                int npc = cnt0 * 4;
                #pragma unroll
                for (int k = 0; k < 4; k++) {
                    int pc = k * 32 + lane;
                    if (pc < npc) sea[warp][pc] = srcp[pc];   // coalesced LDG+STS
                }
                __syncwarp();
            }

            for (int base = beg; base < end; base += 32) {
                int cnt = min(32, end - base);
                // -- prefetch chunk c+1 (coalesced) into registers -------------
                int nbase = base + 32;
                int nidx = nbase + lane;
                int npc = (nbase < end) ? (min(32, end - nbase) * 4) : 0;
                uint4 P[4];
                bool pv[4];
                const uint4* nsrc = &g_ea[(size_t)nbase * 4];
                #pragma unroll
                for (int k = 0; k < 4; k++) {
                    int pc = k * 32 + lane;
                    pv[k] = pc < npc;
                    if (pv[k]) P[k] = nsrc[pc];
                }
                PS psn; bool mf = nidx < end;
                if (mf) {
                    int4 v = g_pack[nidx];
                    float dv = layer2 ? __int_as_float(v.w) : __int_as_float(v.z);
                    float l = g_hs[v.y] + hdn + dv;
                    l = fmaxf(l, ATT_SLOPE * l);
                    float p = __expf(l - mmax);
                    s += p;
                    psn.v.p = p; psn.v.sr = v.y;
                }
                // -- consume current chunk (quads; LDS.128; MLP=4 h loads) -----
                int jq = cnt & ~3;
                for (int jb = 0; jb < jq; jb += 4) {
                    QQ qa, qb;                           // 2 LDS.128 -> 4 (p,sr)
                    qa.u4 = *(const uint4*)&ssp[warp][jb];
                    qb.u4 = *(const uint4*)&ssp[warp][jb + 2];
                    F2U h0, h1, h2, h3;
                    h0.f = g_h[qa.ps[0].v.sr * 32 + lane];
                    h1.f = g_h[qa.ps[1].v.sr * 32 + lane];
                    h2.f = g_h[qb.ps[0].v.sr * 32 + lane];
                    h3.f = g_h[qb.ps[1].v.sr * 32 + lane];
                    #pragma unroll
                    for (int k = 0; k < 4; k++) {
                        float pj = (k < 2) ? qa.ps[k].v.p : qb.ps[k - 2].v.p;
                        F2U hu = (k == 0) ? h0 : (k == 1) ? h1 : (k == 2) ? h2 : h3;
                        const uint4* row = &sea[warp][(jb + k) * 4];
                        U4P r0, r1, r2, r3;              // 4 broadcast LDS.128
                        r0.u4 = row[0]; r1.u4 = row[1]; r2.u4 = row[2]; r3.u4 = row[3];
                        u64 e0 = 0ull, e1 = 0ull;
                        e0 = fma2(r0.pr[0], wd0[0], e0);  e1 = fma2(r0.pr[0], wd1[0], e1);
                        e0 = fma2(r0.pr[1], wd0[1], e0);  e1 = fma2(r0.pr[1], wd1[1], e1);
                        e0 = fma2(r1.pr[0], wd0[2], e0);  e1 = fma2(r1.pr[0], wd1[2], e1);
                        e0 = fma2(r1.pr[1], wd0[3], e0);  e1 = fma2(r1.pr[1], wd1[3], e1);
                        e0 = fma2(r2.pr[0], wd0[4], e0);  e1 = fma2(r2.pr[0], wd1[4], e1);
                        e0 = fma2(r2.pr[1], wd0[5], e0);  e1 = fma2(r2.pr[1], wd1[5], e1);
                        e0 = fma2(r3.pr[0], wd0[6], e0);  e1 = fma2(r3.pr[0], wd1[6], e1);
                        e0 = fma2(r3.pr[1], wd0[7], e0);  e1 = fma2(r3.pr[1], wd1[7], e1);
                        F2U E0; E0.u = e0;
                        F2U E1; E1.u = e1;
                        float v0 = hu.f.x + (E0.f.x + E0.f.y);
                        float v1 = hu.f.y + (E1.f.x + E1.f.y);
                        a0 = fmaxf(a0, pj * v0);
                        a1 = fmaxf(a1, pj * v1);
                    }
                }
                for (int j = jq; j < cnt; j++) {         // tail (< 4 edges)
                    PS q; q.u = ssp[warp][j];
                    F2U hu; hu.f = g_h[q.v.sr * 32 + lane];
                    const uint4* row = &sea[warp][j * 4];
                    U4P r0, r1, r2, r3;
                    r0.u4 = row[0]; r1.u4 = row[1]; r2.u4 = row[2]; r3.u4 = row[3];
                    u64 e0 = 0ull, e1 = 0ull;
                    e0 = fma2(r0.pr[0], wd0[0], e0);  e1 = fma2(r0.pr[0], wd1[0], e1);
                    e0 = fma2(r0.pr[1], wd0[1], e0);  e1 = fma2(r0.pr[1], wd1[1], e1);
                    e0 = fma2(r1.pr[0], wd0[2], e0);  e1 = fma2(r1.pr[0], wd1[2], e1);
                    e0 = fma2(r1.pr[1], wd0[3], e0);  e1 = fma2(r1.pr[1], wd1[3], e1);
                    e0 = fma2(r2.pr[0], wd0[4], e0);  e1 = fma2(r2.pr[0], wd1[4], e1);
                    e0 = fma2(r2.pr[1], wd0[5], e0);  e1 = fma2(r2.pr[1], wd1[5], e1);
                    e0 = fma2(r3.pr[0], wd0[6], e0);  e1 = fma2(r3.pr[0], wd1[6], e1);
                    e0 = fma2(r3.pr[1], wd0[7], e0);  e1 = fma2(r3.pr[1], wd1[7], e1);
                    F2U E0; E0.u = e0;
                    F2U E1; E1.u = e1;
                    float v0 = hu.f.x + (E0.f.x + E0.f.y);
                    float v1 = hu.f.y + (E1.f.x + E1.f.y);
                    a0 = fmaxf(a0, q.v.p * v0);
                    a1 = fmaxf(a1, q.v.p * v1);
                }
                __syncwarp();      // all lanes done reading sea/ssp
                #pragma unroll
                for (int k = 0; k < 4; k++)
                    if (pv[k]) sea[warp][k * 32 + lane] = P[k];
                if (mf) ssp[warp][lane] = psn.u;
                __syncwarp();      // staged data visible before next consume
            }
            #pragma unroll
            for (int o = 16; o; o >>= 1)
                s += __shfl_xor_sync(0xffffffffu, s, o);
            float inv = 1.0f / s;                        // s >= 1 always
            o0 = a0 * inv;
            o1 = a1 * inv;
        }
        o0 += bv.f.x;
        o1 += bv.f.y;
        o0 = fmaxf(o0, ACT_SLOPE * o0);                  // leaky_relu(., 0.01)
        o1 = fmaxf(o1, ACT_SLOPE * o1);
        ((float2*)out)[n * 32 + lane] = make_float2(o0, o1);
    }
}

// ---------------- launch -----------------------------------------------------
extern "C" void kernel_launch(void* const* d_in, const int* in_sizes, int n_in,
                              void* d_out, int out_size) {
    const float* X     = (const float*)d_in[0];
    const int*   ei    = (const int*)  d_in[1];
    const float* eattr = (const float*)d_in[2];
    const float* W1  = (const float*)d_in[3];
    const float* We1 = (const float*)d_in[4];
    const float* as1 = (const float*)d_in[5];
    const float* ad1 = (const float*)d_in[6];
    const float* ae1 = (const float*)d_in[7];
    const float* b1  = (const float*)d_in[8];
    const float* W2  = (const float*)d_in[9];
    const float* We2 = (const float*)d_in[10];
    const float* as2 = (const float*)d_in[11];
    const float* ad2 = (const float*)d_in[12];
    const float* ae2 = (const float*)d_in[13];
    const float* b2  = (const float*)d_in[14];

    const int* srcp = ei;
    const int* dstp = ei + EE;
    float* out = (float*)d_out;

    const int E4B = (EE / 4 + 255) / 256;        // 1563
    const int NB  = (NN + 255) / 256;            // 196
    const int FB  = 592;                         // 4 blocks/SM
    const int GB  = 296;                         // 2 blocks/SM

    // bucketed pack + eattr reorder + dot precompute (once, both layers)
    k_prep<<<NB, 256>>>(We1, ae1, We2, ae2);     // launch 1 (zero + wea)
    k_scatter<<<E4B, 256>>>(srcp, dstp, eattr);  // launch 2

    // layer 1
    k_feat<<<FB, 256>>>(X, W1, as1, ad1, 0);     // launch 3
    k_gat <<<GB, 256>>>(We1, b1, out, 0);        // launch 4 <- ncu profiles this

    // layer 2
    k_feat<<<FB, 256>>>(nullptr, W2, as2, ad2, 1);
    k_gat <<<GB, 256>>>(We2, b2, out, 1);
}

// round 15
// speedup vs baseline: 1.1008x; 1.1008x over previous
#include <cuda_runtime.h>
#include <math_constants.h>

#define NN   50000
#define EE   1600000
#define D    64
#define DE   16
#define CAP  128          // bucket capacity per node (17 sigma above mean deg 32)
#define ATT_SLOPE 0.2f
#define ACT_SLOPE 0.01f

typedef unsigned long long u64;
union F2U { u64 u; float2 f; };
union PS  { u64 u; struct { float p; int sr; } v; };
union QQ  { uint4 u4; PS ps[2]; };     // one LDS.128 -> two (p,sr) records
union U4P { uint4 u4; u64 pr[2]; };    // one LDS.128 -> two f32x2 pairs

__device__ __forceinline__ u64 fma2(u64 a, u64 b, u64 c) {
    u64 d; asm("fma.rn.f32x2 %0, %1, %2, %3;" : "=l"(d) : "l"(a), "l"(b), "l"(c));
    return d;
}
__device__ __forceinline__ u64 pack2(float x, float y) {
    F2U t; t.f = make_float2(x, y); return t.u;
}

// ---------------- scratch (device globals; no allocation allowed) -----------
__device__ float2 g_h [NN * 32];     // transformed features, dim pairs (2l,2l+1)
__device__ float2 g_c1[NN * 32];     // layer-1 output
__device__ float  g_hs[NN];
__device__ float  g_hd[NN];
__device__ int4   g_pack[NN * CAP];  // {eid, src, dot1(asint), dot2(asint)}
__device__ int    g_cnt[NN];         // per-node edge count (cursor)
__device__ float  g_wea1[DE], g_wea2[DE];

// ---------------- prep: zero counters + wea = We@ae (merged: 1 launch) ------
__global__ void k_prep(const float* __restrict__ We1, const float* __restrict__ ae1,
                       const float* __restrict__ We2, const float* __restrict__ ae2) {
    int i = blockIdx.x * blockDim.x + threadIdx.x;
    if (i < NN) g_cnt[i] = 0;
    if (blockIdx.x == 0 && threadIdx.x < 2 * DE) {
        int t = threadIdx.x;
        if (t < DE) {
            float a = 0.f;
            #pragma unroll
            for (int d = 0; d < D; d++) a = fmaf(We1[t * D + d], ae1[d], a);
            g_wea1[t] = a;
        } else {
            int j = t - DE;
            float a = 0.f;
            #pragma unroll
            for (int d = 0; d < D; d++) a = fmaf(We2[j * D + d], ae2[d], a);
            g_wea2[j] = a;
        }
    }
}

// scatter into fixed buckets: packed record per edge (one STG.128)
__global__ void k_scatter(const int* __restrict__ src, const int* __restrict__ dst,
                          const float* __restrict__ eattr) {
    __shared__ float sw1[DE], sw2[DE];
    if (threadIdx.x < DE) sw1[threadIdx.x] = g_wea1[threadIdx.x];
    else if (threadIdx.x < 2 * DE) sw2[threadIdx.x - DE] = g_wea2[threadIdx.x - DE];
    __syncthreads();
    int i = blockIdx.x * blockDim.x + threadIdx.x;
    if (i < EE / 4) {
        int4 dv = ((const int4*)dst)[i];
        int4 sv = ((const int4*)src)[i];
        const int* dp = &dv.x;
        const int* sp = &sv.x;
        #pragma unroll
        for (int r = 0; r < 4; r++) {
            int e = 4 * i + r;
            const float4* ea4 = (const float4*)(eattr + (size_t)e * DE);
            float4 A = ea4[0], B = ea4[1], C = ea4[2], Dd = ea4[3];
            float d1 = 0.f, d2 = 0.f;
            #pragma unroll
            for (int k = 0; k < 4; k++) { d1 = fmaf((&A.x)[k],  sw1[k],      d1); d2 = fmaf((&A.x)[k],  sw2[k],      d2); }
            #pragma unroll
            for (int k = 0; k < 4; k++) { d1 = fmaf((&B.x)[k],  sw1[k + 4],  d1); d2 = fmaf((&B.x)[k],  sw2[k + 4],  d2); }
            #pragma unroll
            for (int k = 0; k < 4; k++) { d1 = fmaf((&C.x)[k],  sw1[k + 8],  d1); d2 = fmaf((&C.x)[k],  sw2[k + 8],  d2); }
            #pragma unroll
            for (int k = 0; k < 4; k++) { d1 = fmaf((&Dd.x)[k], sw1[k + 12], d1); d2 = fmaf((&Dd.x)[k], sw2[k + 12], d2); }
            int dn = dp[r];
            int p = atomicAdd(&g_cnt[dn], 1);
            g_pack[dn * CAP + p] = make_int4(e, sp[r], __float_as_int(d1), __float_as_int(d2));
        }
    }
}

// ---------------- feature transform: h = x@W, hs = h.a_s, hd = h.a_d --------
__global__ void __launch_bounds__(256) k_feat(const float* __restrict__ xin,
                                              const float* __restrict__ W,
                                              const float* __restrict__ a_s,
                                              const float* __restrict__ a_d,
                                              int use_c1) {
    __shared__ u64 sW2[D * 32];
    __shared__ float sx[8][4][D];
    __shared__ u64 sas2[32], sad2[32];
    const float* __restrict__ x = use_c1 ? (const float*)g_c1 : xin;
    int tid = threadIdx.x;
    for (int i = tid; i < D * 32; i += 256) sW2[i] = ((const u64*)W)[i];
    if (tid < 32) { sas2[tid] = ((const u64*)a_s)[tid]; sad2[tid] = ((const u64*)a_d)[tid]; }
    __syncthreads();
    int warp = tid >> 5, lane = tid & 31;
    F2U asv; asv.u = sas2[lane];
    F2U adv; adv.u = sad2[lane];
    int gw = blockIdx.x * 8 + warp;
    int nw = gridDim.x * 8;
    for (int r0 = gw * 4; r0 < NN; r0 += nw * 4) {
        #pragma unroll
        for (int r = 0; r < 4; r++) {
            int row = r0 + r;
            if (row < NN) {
                sx[warp][r][lane]      = x[row * D + lane];
                sx[warp][r][lane + 32] = x[row * D + lane + 32];
            }
        }
        __syncwarp();
        F2U acc[4];
        #pragma unroll
        for (int r = 0; r < 4; r++) acc[r].u = 0ull;
        #pragma unroll
        for (int k = 0; k < D; k++) {
            u64 wp = sW2[k * 32 + lane];
            #pragma unroll
            for (int r = 0; r < 4; r++) {
                float xv = sx[warp][r][k];
                acc[r].u = fma2(pack2(xv, xv), wp, acc[r].u);
            }
        }
        #pragma unroll
        for (int r = 0; r < 4; r++) {
            int row = r0 + r;
            if (row < NN) {
                g_h[row * 32 + lane] = acc[r].f;
                float ps = acc[r].f.x * asv.f.x + acc[r].f.y * asv.f.y;
                float pd = acc[r].f.x * adv.f.x + acc[r].f.y * adv.f.y;
                #pragma unroll
                for (int o = 16; o; o >>= 1) {
                    ps += __shfl_xor_sync(0xffffffffu, ps, o);
                    pd += __shfl_xor_sync(0xffffffffu, pd, o);
                }
                if (lane == 0) { g_hs[row] = ps; g_hd[row] = pd; }
            }
        }
        __syncwarp();
    }
}

// ---------------- fused GAT: quad-pipelined consume (h prefetched 1 quad ahead)
// warp per dst node; lane owns dim pair (2l,2l+1); We in registers.
// Stage is direct (LDG->STS once per chunk); consume prefetches next quad's
// (p,sr)+h rows while the current quad's fma chains run.
__global__ void __launch_bounds__(256, 2) k_gat(const float* __restrict__ edge_attr,
                                                const float* __restrict__ We,
                                                const float* __restrict__ bias,
                                                float* __restrict__ dout,
                                                int layer2) {
    __shared__ uint4 sea[8][32][5];   // [warp][edge][4 used + 1 pad] 80B row stride
    __shared__ u64   ssp[8][34];      // packed (p,sr); paired LDS.128 reads
    __shared__ u64   sb2[32];
    float* __restrict__ out = layer2 ? dout : (float*)g_c1;
    int tid = threadIdx.x, lane = tid & 31, warp = tid >> 5;
    if (tid < 32) sb2[tid] = ((const u64*)bias)[tid];
    __syncthreads();

    // register-resident We k-pairs for this lane's two dims
    int d0 = 2 * lane, d1 = d0 + 1;
    u64 wd0[8], wd1[8];
    #pragma unroll
    for (int j = 0; j < 8; j++) {
        wd0[j] = pack2(We[(2 * j) * D + d0], We[(2 * j + 1) * D + d0]);
        wd1[j] = pack2(We[(2 * j) * D + d1], We[(2 * j + 1) * D + d1]);
    }
    F2U bv; bv.u = sb2[lane];

    int gw = blockIdx.x * 8 + warp;
    int nw = gridDim.x * 8;

    for (int n = gw; n < NN; n += nw) {
        int beg = n * CAP, end = beg + g_cnt[n];
        float o0, o1;
        if (beg == end) {
            o0 = 0.f; o1 = 0.f;
        } else {
            float hdn = g_hd[n];
            // ---- pass 1: segment max of logits (lane-parallel) --------------
            float mmax = -CUDART_INF_F;
            for (int idx = beg + lane; idx < end; idx += 32) {
                int4 v = g_pack[idx];
                float dv = layer2 ? __int_as_float(v.w) : __int_as_float(v.z);
                float l = g_hs[v.y] + hdn + dv;
                l = fmaxf(l, ATT_SLOPE * l);            // leaky_relu(l, 0.2)
                mmax = fmaxf(mmax, l);
            }
            #pragma unroll
            for (int o = 16; o; o >>= 1)
                mmax = fmaxf(mmax, __shfl_xor_sync(0xffffffffu, mmax, o));

            // ---- pass 2: stage + quad-pipelined aggregate -------------------
            float s = 0.f;
            float a0 = -CUDART_INF_F, a1 = -CUDART_INF_F;

            for (int base = beg; base < end; base += 32) {
                int cnt = min(32, end - base);
                int idx = base + lane;
                // -- stage chunk directly: metadata + eattr gather -------------
                if (idx < end) {
                    int4 v = g_pack[idx];
                    float dv = layer2 ? __int_as_float(v.w) : __int_as_float(v.z);
                    float l = g_hs[v.y] + hdn + dv;
                    l = fmaxf(l, ATT_SLOPE * l);
                    float p = __expf(l - mmax);         // arg <= 0
                    s += p;
                    PS ps; ps.v.p = p; ps.v.sr = v.y;
                    ssp[warp][lane] = ps.u;
                    const uint4* ea4 = (const uint4*)(edge_attr + (size_t)v.x * DE);
                    uint4 t0 = ea4[0], t1 = ea4[1], t2 = ea4[2], t3 = ea4[3];
                    uint4* w4 = &sea[warp][lane][0];    // STS.128, conflict-free
                    w4[0] = t0; w4[1] = t1; w4[2] = t2; w4[3] = t3;
                }
                __syncwarp();
                // -- consume: prefetch next quad's (p,sr)+h during current ----
                int jq = cnt & ~3;
                QQ qa, qb; F2U h0, h1, h2, h3;
                if (jq > 0) {
                    qa.u4 = *(const uint4*)&ssp[warp][0];
                    qb.u4 = *(const uint4*)&ssp[warp][2];
                    h0.f = g_h[qa.ps[0].v.sr * 32 + lane];
                    h1.f = g_h[qa.ps[1].v.sr * 32 + lane];
                    h2.f = g_h[qb.ps[0].v.sr * 32 + lane];
                    h3.f = g_h[qb.ps[1].v.sr * 32 + lane];
                }
                for (int jb = 0; jb < jq; jb += 4) {
                    int nj = min(jb + 4, jq - 4);       // clamped: last iter reloads self
                    QQ qan, qbn; F2U hn0, hn1, hn2, hn3;
                    qan.u4 = *(const uint4*)&ssp[warp][nj];
                    qbn.u4 = *(const uint4*)&ssp[warp][nj + 2];
                    hn0.f = g_h[qan.ps[0].v.sr * 32 + lane];
                    hn1.f = g_h[qan.ps[1].v.sr * 32 + lane];
                    hn2.f = g_h[qbn.ps[0].v.sr * 32 + lane];
                    hn3.f = g_h[qbn.ps[1].v.sr * 32 + lane];
                    #pragma unroll
                    for (int k = 0; k < 4; k++) {
                        float pj = (k < 2) ? qa.ps[k].v.p : qb.ps[k - 2].v.p;
                        F2U hu = (k == 0) ? h0 : (k == 1) ? h1 : (k == 2) ? h2 : h3;
                        const uint4* row = &sea[warp][jb + k][0];
                        U4P r0, r1, r2, r3;              // 4 broadcast LDS.128
                        r0.u4 = row[0]; r1.u4 = row[1]; r2.u4 = row[2]; r3.u4 = row[3];
                        u64 e0 = 0ull, e1 = 0ull;
                        e0 = fma2(r0.pr[0], wd0[0], e0);  e1 = fma2(r0.pr[0], wd1[0], e1);
                        e0 = fma2(r0.pr[1], wd0[1], e0);  e1 = fma2(r0.pr[1], wd1[1], e1);
                        e0 = fma2(r1.pr[0], wd0[2], e0);  e1 = fma2(r1.pr[0], wd1[2], e1);
                        e0 = fma2(r1.pr[1], wd0[3], e0);  e1 = fma2(r1.pr[1], wd1[3], e1);
                        e0 = fma2(r2.pr[0], wd0[4], e0);  e1 = fma2(r2.pr[0], wd1[4], e1);
                        e0 = fma2(r2.pr[1], wd0[5], e0);  e1 = fma2(r2.pr[1], wd1[5], e1);
                        e0 = fma2(r3.pr[0], wd0[6], e0);  e1 = fma2(r3.pr[0], wd1[6], e1);
                        e0 = fma2(r3.pr[1], wd0[7], e0);  e1 = fma2(r3.pr[1], wd1[7], e1);
                        F2U E0; E0.u = e0;
                        F2U E1; E1.u = e1;
                        float v0 = hu.f.x + (E0.f.x + E0.f.y);
                        float v1 = hu.f.y + (E1.f.x + E1.f.y);
                        a0 = fmaxf(a0, pj * v0);
                        a1 = fmaxf(a1, pj * v1);
                    }
                    qa = qan; qb = qbn;
                    h0 = hn0; h1 = hn1; h2 = hn2; h3 = hn3;
                }
                for (int j = jq; j < cnt; j++) {         // tail (< 4 edges)
                    PS q; q.u = ssp[warp][j];
                    F2U hu; hu.f = g_h[q.v.sr * 32 + lane];
                    const uint4* row = &sea[warp][j][0];
                    U4P r0, r1, r2, r3;
                    r0.u4 = row[0]; r1.u4 = row[1]; r2.u4 = row[2]; r3.u4 = row[3];
                    u64 e0 = 0ull, e1 = 0ull;
                    e0 = fma2(r0.pr[0], wd0[0], e0);  e1 = fma2(r0.pr[0], wd1[0], e1);
                    e0 = fma2(r0.pr[1], wd0[1], e0);  e1 = fma2(r0.pr[1], wd1[1], e1);
                    e0 = fma2(r1.pr[0], wd0[2], e0);  e1 = fma2(r1.pr[0], wd1[2], e1);
                    e0 = fma2(r1.pr[1], wd0[3], e0);  e1 = fma2(r1.pr[1], wd1[3], e1);
                    e0 = fma2(r2.pr[0], wd0[4], e0);  e1 = fma2(r2.pr[0], wd1[4], e1);
                    e0 = fma2(r2.pr[1], wd0[5], e0);  e1 = fma2(r2.pr[1], wd1[5], e1);
                    e0 = fma2(r3.pr[0], wd0[6], e0);  e1 = fma2(r3.pr[0], wd1[6], e1);
                    e0 = fma2(r3.pr[1], wd0[7], e0);  e1 = fma2(r3.pr[1], wd1[7], e1);
                    F2U E0; E0.u = e0;
                    F2U E1; E1.u = e1;
                    float v0 = hu.f.x + (E0.f.x + E0.f.y);
                    float v1 = hu.f.y + (E1.f.x + E1.f.y);
                    a0 = fmaxf(a0, q.v.p * v0);
                    a1 = fmaxf(a1, q.v.p * v1);
                }
                __syncwarp();      // lanes done with sea/ssp before next stage
            }
            #pragma unroll
            for (int o = 16; o; o >>= 1)
                s += __shfl_xor_sync(0xffffffffu, s, o);
            float inv = 1.0f / s;                        // s >= 1 always
            o0 = a0 * inv;
            o1 = a1 * inv;
        }
        o0 += bv.f.x;
        o1 += bv.f.y;
        o0 = fmaxf(o0, ACT_SLOPE * o0);                  // leaky_relu(., 0.01)
        o1 = fmaxf(o1, ACT_SLOPE * o1);
        ((float2*)out)[n * 32 + lane] = make_float2(o0, o1);
    }
}

// ---------------- launch -----------------------------------------------------
extern "C" void kernel_launch(void* const* d_in, const int* in_sizes, int n_in,
                              void* d_out, int out_size) {
    const float* X     = (const float*)d_in[0];
    const int*   ei    = (const int*)  d_in[1];
    const float* eattr = (const float*)d_in[2];
    const float* W1  = (const float*)d_in[3];
    const float* We1 = (const float*)d_in[4];
    const float* as1 = (const float*)d_in[5];
    const float* ad1 = (const float*)d_in[6];
    const float* ae1 = (const float*)d_in[7];
    const float* b1  = (const float*)d_in[8];
    const float* W2  = (const float*)d_in[9];
    const float* We2 = (const float*)d_in[10];
    const float* as2 = (const float*)d_in[11];
    const float* ad2 = (const float*)d_in[12];
    const float* ae2 = (const float*)d_in[13];
    const float* b2  = (const float*)d_in[14];

    const int* srcp = ei;
    const int* dstp = ei + EE;
    float* out = (float*)d_out;

    const int E4B = (EE / 4 + 255) / 256;        // 1563
    const int NB  = (NN + 255) / 256;            // 196
    const int FB  = 592;                         // 4 blocks/SM
    const int GB  = 296;                         // 2 blocks/SM

    // bucketed pack + per-edge dot precompute (once per launch, both layers)
    k_prep<<<NB, 256>>>(We1, ae1, We2, ae2);     // launch 1 (zero + wea)
    k_scatter<<<E4B, 256>>>(srcp, dstp, eattr);  // launch 2

    // layer 1
    k_feat<<<FB, 256>>>(X, W1, as1, ad1, 0);     // launch 3
    k_gat <<<GB, 256>>>(eattr, We1, b1, out, 0); // launch 4 <- ncu profiles this

    // layer 2
    k_feat<<<FB, 256>>>(nullptr, W2, as2, ad2, 1);
    k_gat <<<GB, 256>>>(eattr, We2, b2, out, 1);
}

// round 16
// speedup vs baseline: 1.1621x; 1.0558x over previous
#include <cuda_runtime.h>
#include <math_constants.h>

#define NN   50000
#define EE   1600000
#define D    64
#define DE   16
#define CAP  128          // bucket capacity per node (17 sigma above mean deg 32)
#define ATT_SLOPE 0.2f
#define ACT_SLOPE 0.01f

typedef unsigned long long u64;
union F2U { u64 u; float2 f; };
union PS  { u64 u; struct { float p; int sr; } v; };
union QQ  { uint4 u4; PS ps[2]; };     // one LDS.128 -> two (p,sr) records
union U4P { uint4 u4; u64 pr[2]; };    // one LDS.128 -> two f32x2 pairs

__device__ __forceinline__ u64 fma2(u64 a, u64 b, u64 c) {
    u64 d; asm("fma.rn.f32x2 %0, %1, %2, %3;" : "=l"(d) : "l"(a), "l"(b), "l"(c));
    return d;
}
__device__ __forceinline__ u64 pack2(float x, float y) {
    F2U t; t.f = make_float2(x, y); return t.u;
}

// ---------------- scratch (device globals; no allocation allowed) -----------
__device__ float2 g_h [NN * 32];     // transformed features, dim pairs (2l,2l+1)
__device__ float2 g_c1[NN * 32];     // layer-1 output
__device__ float  g_hs[NN];
__device__ float  g_hd[NN];
__device__ int4   g_pack[NN * CAP];  // {eid, src, dot1(asint), dot2(asint)}
__device__ int    g_cnt[NN];         // per-node edge count (cursor)
__device__ float  g_wea1[DE], g_wea2[DE];

// ---------------- prep: zero counters + wea = We@ae (merged: 1 launch) ------
__global__ void k_prep(const float* __restrict__ We1, const float* __restrict__ ae1,
                       const float* __restrict__ We2, const float* __restrict__ ae2) {
    int i = blockIdx.x * blockDim.x + threadIdx.x;
    if (i < NN) g_cnt[i] = 0;
    if (blockIdx.x == 0 && threadIdx.x < 2 * DE) {
        int t = threadIdx.x;
        if (t < DE) {
            float a = 0.f;
            #pragma unroll
            for (int d = 0; d < D; d++) a = fmaf(We1[t * D + d], ae1[d], a);
            g_wea1[t] = a;
        } else {
            int j = t - DE;
            float a = 0.f;
            #pragma unroll
            for (int d = 0; d < D; d++) a = fmaf(We2[j * D + d], ae2[d], a);
            g_wea2[j] = a;
        }
    }
}

// scatter into fixed buckets: packed record per edge (one STG.128)
__global__ void k_scatter(const int* __restrict__ src, const int* __restrict__ dst,
                          const float* __restrict__ eattr) {
    __shared__ float sw1[DE], sw2[DE];
    if (threadIdx.x < DE) sw1[threadIdx.x] = g_wea1[threadIdx.x];
    else if (threadIdx.x < 2 * DE) sw2[threadIdx.x - DE] = g_wea2[threadIdx.x - DE];
    __syncthreads();
    int i = blockIdx.x * blockDim.x + threadIdx.x;
    if (i < EE / 4) {
        int4 dv = ((const int4*)dst)[i];
        int4 sv = ((const int4*)src)[i];
        const int* dp = &dv.x;
        const int* sp = &sv.x;
        #pragma unroll
        for (int r = 0; r < 4; r++) {
            int e = 4 * i + r;
            const float4* ea4 = (const float4*)(eattr + (size_t)e * DE);
            float4 A = ea4[0], B = ea4[1], C = ea4[2], Dd = ea4[3];
            float d1 = 0.f, d2 = 0.f;
            #pragma unroll
            for (int k = 0; k < 4; k++) { d1 = fmaf((&A.x)[k],  sw1[k],      d1); d2 = fmaf((&A.x)[k],  sw2[k],      d2); }
            #pragma unroll
            for (int k = 0; k < 4; k++) { d1 = fmaf((&B.x)[k],  sw1[k + 4],  d1); d2 = fmaf((&B.x)[k],  sw2[k + 4],  d2); }
            #pragma unroll
            for (int k = 0; k < 4; k++) { d1 = fmaf((&C.x)[k],  sw1[k + 8],  d1); d2 = fmaf((&C.x)[k],  sw2[k + 8],  d2); }
            #pragma unroll
            for (int k = 0; k < 4; k++) { d1 = fmaf((&Dd.x)[k], sw1[k + 12], d1); d2 = fmaf((&Dd.x)[k], sw2[k + 12], d2); }
            int dn = dp[r];
            int p = atomicAdd(&g_cnt[dn], 1);
            g_pack[dn * CAP + p] = make_int4(e, sp[r], __float_as_int(d1), __float_as_int(d2));
        }
    }
}

// ---------------- feature transform: h = x@W, hs = h.a_s, hd = h.a_d --------
__global__ void __launch_bounds__(256) k_feat(const float* __restrict__ xin,
                                              const float* __restrict__ W,
                                              const float* __restrict__ a_s,
                                              const float* __restrict__ a_d,
                                              int use_c1) {
    __shared__ u64 sW2[D * 32];
    __shared__ float sx[8][4][D];
    __shared__ u64 sas2[32], sad2[32];
    const float* __restrict__ x = use_c1 ? (const float*)g_c1 : xin;
    int tid = threadIdx.x;
    for (int i = tid; i < D * 32; i += 256) sW2[i] = ((const u64*)W)[i];
    if (tid < 32) { sas2[tid] = ((const u64*)a_s)[tid]; sad2[tid] = ((const u64*)a_d)[tid]; }
    __syncthreads();
    int warp = tid >> 5, lane = tid & 31;
    F2U asv; asv.u = sas2[lane];
    F2U adv; adv.u = sad2[lane];
    int gw = blockIdx.x * 8 + warp;
    int nw = gridDim.x * 8;
    for (int r0 = gw * 4; r0 < NN; r0 += nw * 4) {
        #pragma unroll
        for (int r = 0; r < 4; r++) {
            int row = r0 + r;
            if (row < NN) {
                sx[warp][r][lane]      = x[row * D + lane];
                sx[warp][r][lane + 32] = x[row * D + lane + 32];
            }
        }
        __syncwarp();
        F2U acc[4];
        #pragma unroll
        for (int r = 0; r < 4; r++) acc[r].u = 0ull;
        #pragma unroll
        for (int k = 0; k < D; k++) {
            u64 wp = sW2[k * 32 + lane];
            #pragma unroll
            for (int r = 0; r < 4; r++) {
                float xv = sx[warp][r][k];
                acc[r].u = fma2(pack2(xv, xv), wp, acc[r].u);
            }
        }
        #pragma unroll
        for (int r = 0; r < 4; r++) {
            int row = r0 + r;
            if (row < NN) {
                g_h[row * 32 + lane] = acc[r].f;
                float ps = acc[r].f.x * asv.f.x + acc[r].f.y * asv.f.y;
                float pd = acc[r].f.x * adv.f.x + acc[r].f.y * adv.f.y;
                #pragma unroll
                for (int o = 16; o; o >>= 1) {
                    ps += __shfl_xor_sync(0xffffffffu, ps, o);
                    pd += __shfl_xor_sync(0xffffffffu, pd, o);
                }
                if (lane == 0) { g_hs[row] = ps; g_hd[row] = pd; }
            }
        }
        __syncwarp();
    }
}

// ---------------- fused GAT: register-lean, 3 blocks/SM ----------------------
// warp per dst node; lane owns dim pair (2l,2l+1); We in registers (32 regs).
// Direct stage (LDG->STS per chunk) + simple-quad consume (R13's consume):
// 2x LDS.128 (p,sr) + 4 independent h-row LDGs (MLP=4) + fma block per quad.
__global__ void __launch_bounds__(256, 3) k_gat(const float* __restrict__ edge_attr,
                                                const float* __restrict__ We,
                                                const float* __restrict__ bias,
                                                float* __restrict__ dout,
                                                int layer2) {
    __shared__ uint4 sea[8][32][5];   // [warp][edge][4 used + 1 pad] 80B row stride
    __shared__ u64   ssp[8][34];      // packed (p,sr); paired LDS.128 reads
    __shared__ u64   sb2[32];
    float* __restrict__ out = layer2 ? dout : (float*)g_c1;
    int tid = threadIdx.x, lane = tid & 31, warp = tid >> 5;
    if (tid < 32) sb2[tid] = ((const u64*)bias)[tid];
    __syncthreads();

    // register-resident We k-pairs for this lane's two dims
    int d0 = 2 * lane, d1 = d0 + 1;
    u64 wd0[8], wd1[8];
    #pragma unroll
    for (int j = 0; j < 8; j++) {
        wd0[j] = pack2(We[(2 * j) * D + d0], We[(2 * j + 1) * D + d0]);
        wd1[j] = pack2(We[(2 * j) * D + d1], We[(2 * j + 1) * D + d1]);
    }
    F2U bv; bv.u = sb2[lane];

    int gw = blockIdx.x * 8 + warp;
    int nw = gridDim.x * 8;

    for (int n = gw; n < NN; n += nw) {
        int beg = n * CAP, end = beg + g_cnt[n];
        float o0, o1;
        if (beg == end) {
            o0 = 0.f; o1 = 0.f;
        } else {
            float hdn = g_hd[n];
            // ---- pass 1: segment max of logits (lane-parallel) --------------
            float mmax = -CUDART_INF_F;
            for (int idx = beg + lane; idx < end; idx += 32) {
                int4 v = g_pack[idx];
                float dv = layer2 ? __int_as_float(v.w) : __int_as_float(v.z);
                float l = g_hs[v.y] + hdn + dv;
                l = fmaxf(l, ATT_SLOPE * l);            // leaky_relu(l, 0.2)
                mmax = fmaxf(mmax, l);
            }
            #pragma unroll
            for (int o = 16; o; o >>= 1)
                mmax = fmaxf(mmax, __shfl_xor_sync(0xffffffffu, mmax, o));

            // ---- pass 2: direct stage + simple-quad consume -----------------
            float s = 0.f;
            float a0 = -CUDART_INF_F, a1 = -CUDART_INF_F;

            for (int base = beg; base < end; base += 32) {
                int cnt = min(32, end - base);
                int idx = base + lane;
                // -- stage chunk: metadata + eattr gather ----------------------
                if (idx < end) {
                    int4 v = g_pack[idx];
                    float dv = layer2 ? __int_as_float(v.w) : __int_as_float(v.z);
                    float l = g_hs[v.y] + hdn + dv;
                    l = fmaxf(l, ATT_SLOPE * l);
                    float p = __expf(l - mmax);         // arg <= 0
                    s += p;
                    PS ps; ps.v.p = p; ps.v.sr = v.y;
                    ssp[warp][lane] = ps.u;
                    const uint4* ea4 = (const uint4*)(edge_attr + (size_t)v.x * DE);
                    uint4 t0 = ea4[0], t1 = ea4[1], t2 = ea4[2], t3 = ea4[3];
                    uint4* w4 = &sea[warp][lane][0];    // STS.128, conflict-free
                    w4[0] = t0; w4[1] = t1; w4[2] = t2; w4[3] = t3;
                }
                __syncwarp();
                // -- consume (quads; LDS.128; MLP=4 h loads) -------------------
                int jq = cnt & ~3;
                for (int jb = 0; jb < jq; jb += 4) {
                    QQ qa, qb;                           // 2 LDS.128 -> 4 (p,sr)
                    qa.u4 = *(const uint4*)&ssp[warp][jb];
                    qb.u4 = *(const uint4*)&ssp[warp][jb + 2];
                    F2U h0, h1, h2, h3;
                    h0.f = g_h[qa.ps[0].v.sr * 32 + lane];
                    h1.f = g_h[qa.ps[1].v.sr * 32 + lane];
                    h2.f = g_h[qb.ps[0].v.sr * 32 + lane];
                    h3.f = g_h[qb.ps[1].v.sr * 32 + lane];
                    #pragma unroll
                    for (int k = 0; k < 4; k++) {
                        float pj = (k < 2) ? qa.ps[k].v.p : qb.ps[k - 2].v.p;
                        F2U hu = (k == 0) ? h0 : (k == 1) ? h1 : (k == 2) ? h2 : h3;
                        const uint4* row = &sea[warp][jb + k][0];
                        U4P r0, r1, r2, r3;              // 4 broadcast LDS.128
                        r0.u4 = row[0]; r1.u4 = row[1]; r2.u4 = row[2]; r3.u4 = row[3];
                        u64 e0 = 0ull, e1 = 0ull;
                        e0 = fma2(r0.pr[0], wd0[0], e0);  e1 = fma2(r0.pr[0], wd1[0], e1);
                        e0 = fma2(r0.pr[1], wd0[1], e0);  e1 = fma2(r0.pr[1], wd1[1], e1);
                        e0 = fma2(r1.pr[0], wd0[2], e0);  e1 = fma2(r1.pr[0], wd1[2], e1);
                        e0 = fma2(r1.pr[1], wd0[3], e0);  e1 = fma2(r1.pr[1], wd1[3], e1);
                        e0 = fma2(r2.pr[0], wd0[4], e0);  e1 = fma2(r2.pr[0], wd1[4], e1);
                        e0 = fma2(r2.pr[1], wd0[5], e0);  e1 = fma2(r2.pr[1], wd1[5], e1);
                        e0 = fma2(r3.pr[0], wd0[6], e0);  e1 = fma2(r3.pr[0], wd1[6], e1);
                        e0 = fma2(r3.pr[1], wd0[7], e0);  e1 = fma2(r3.pr[1], wd1[7], e1);
                        F2U E0; E0.u = e0;
                        F2U E1; E1.u = e1;
                        float v0 = hu.f.x + (E0.f.x + E0.f.y);
                        float v1 = hu.f.y + (E1.f.x + E1.f.y);
                        a0 = fmaxf(a0, pj * v0);
                        a1 = fmaxf(a1, pj * v1);
                    }
                }
                for (int j = jq; j < cnt; j++) {         // tail (< 4 edges)
                    PS q; q.u = ssp[warp][j];
                    F2U hu; hu.f = g_h[q.v.sr * 32 + lane];
                    const uint4* row = &sea[warp][j][0];
                    U4P r0, r1, r2, r3;
                    r0.u4 = row[0]; r1.u4 = row[1]; r2.u4 = row[2]; r3.u4 = row[3];
                    u64 e0 = 0ull, e1 = 0ull;
                    e0 = fma2(r0.pr[0], wd0[0], e0);  e1 = fma2(r0.pr[0], wd1[0], e1);
                    e0 = fma2(r0.pr[1], wd0[1], e0);  e1 = fma2(r0.pr[1], wd1[1], e1);
                    e0 = fma2(r1.pr[0], wd0[2], e0);  e1 = fma2(r1.pr[0], wd1[2], e1);
                    e0 = fma2(r1.pr[1], wd0[3], e0);  e1 = fma2(r1.pr[1], wd1[3], e1);
                    e0 = fma2(r2.pr[0], wd0[4], e0);  e1 = fma2(r2.pr[0], wd1[4], e1);
                    e0 = fma2(r2.pr[1], wd0[5], e0);  e1 = fma2(r2.pr[1], wd1[5], e1);
                    e0 = fma2(r3.pr[0], wd0[6], e0);  e1 = fma2(r3.pr[0], wd1[6], e1);
                    e0 = fma2(r3.pr[1], wd0[7], e0);  e1 = fma2(r3.pr[1], wd1[7], e1);
                    F2U E0; E0.u = e0;
                    F2U E1; E1.u = e1;
                    float v0 = hu.f.x + (E0.f.x + E0.f.y);
                    float v1 = hu.f.y + (E1.f.x + E1.f.y);
                    a0 = fmaxf(a0, q.v.p * v0);
                    a1 = fmaxf(a1, q.v.p * v1);
                }
                __syncwarp();      // lanes done with sea/ssp before next stage
            }
            #pragma unroll
            for (int o = 16; o; o >>= 1)
                s += __shfl_xor_sync(0xffffffffu, s, o);
            float inv = 1.0f / s;                        // s >= 1 always
            o0 = a0 * inv;
            o1 = a1 * inv;
        }
        o0 += bv.f.x;
        o1 += bv.f.y;
        o0 = fmaxf(o0, ACT_SLOPE * o0);                  // leaky_relu(., 0.01)
        o1 = fmaxf(o1, ACT_SLOPE * o1);
        ((float2*)out)[n * 32 + lane] = make_float2(o0, o1);
    }
}

// ---------------- launch -----------------------------------------------------
extern "C" void kernel_launch(void* const* d_in, const int* in_sizes, int n_in,
                              void* d_out, int out_size) {
    const float* X     = (const float*)d_in[0];
    const int*   ei    = (const int*)  d_in[1];
    const float* eattr = (const float*)d_in[2];
    const float* W1  = (const float*)d_in[3];
    const float* We1 = (const float*)d_in[4];
    const float* as1 = (const float*)d_in[5];
    const float* ad1 = (const float*)d_in[6];
    const float* ae1 = (const float*)d_in[7];
    const float* b1  = (const float*)d_in[8];
    const float* W2  = (const float*)d_in[9];
    const float* We2 = (const float*)d_in[10];
    const float* as2 = (const float*)d_in[11];
    const float* ad2 = (const float*)d_in[12];
    const float* ae2 = (const float*)d_in[13];
    const float* b2  = (const float*)d_in[14];

    const int* srcp = ei;
    const int* dstp = ei + EE;
    float* out = (float*)d_out;

    const int E4B = (EE / 4 + 255) / 256;        // 1563
    const int NB  = (NN + 255) / 256;            // 196
    const int FB  = 592;                         // 4 blocks/SM
    const int GB  = 444;                         // 3 blocks/SM

    // bucketed pack + per-edge dot precompute (once per launch, both layers)
    k_prep<<<NB, 256>>>(We1, ae1, We2, ae2);     // launch 1 (zero + wea)
    k_scatter<<<E4B, 256>>>(srcp, dstp, eattr);  // launch 2

    // layer 1
    k_feat<<<FB, 256>>>(X, W1, as1, ad1, 0);     // launch 3
    k_gat <<<GB, 256>>>(eattr, We1, b1, out, 0); // launch 4 <- ncu profiles this

    // layer 2
    k_feat<<<FB, 256>>>(nullptr, W2, as2, ad2, 1);
    k_gat <<<GB, 256>>>(eattr, We2, b2, out, 1);
}